// round 1
// baseline (speedup 1.0000x reference)
#include <cuda_runtime.h>
#include <cuda_fp16.h>

#define NN 50000
#define EE 800000
#define RR 8
#define BB 8
#define HH 128
#define LL 3
#define FDIM 6
#define KTOT 1152   // R*H + H (root folded in)
#define BN_EPS 1e-5f

// ---------------- scratch (static device memory; no allocations allowed) ----
__device__ float  g_s[NN * RR * HH];        // per-(node,rel) feature sums (204.8 MB)
__device__ float  g_h[NN * HH];             // pre-BN layer output
__device__ int    g_cnt[NN * RR];
__device__ float  g_inv[NN * RR];           // 1/cnt, 0 if cnt==0
__device__ __half g_Wh[KTOT * HH];          // [Wcat | root] in fp16 for current layer
__device__ double g_sum[HH], g_sumsq[HH];

// ---------------- kernels ---------------------------------------------------

__global__ void init_x_kernel(float* __restrict__ x,
                              const int* __restrict__ x_ids,
                              const float* __restrict__ node_feat,
                              const float* __restrict__ emb,
                              const float* __restrict__ feat_w,
                              const float* __restrict__ feat_b,
                              const float* __restrict__ virt) {
    int n = blockIdx.x, o = threadIdx.x;
    float f = feat_b[o];
#pragma unroll
    for (int d = 0; d < FDIM; d++)
        f += node_feat[n * FDIM + d] * feat_w[o * FDIM + d];
    x[n * HH + o] = emb[x_ids[n] * HH + o] + fmaxf(f, 0.f) + virt[o];
}

__global__ void zero_cnt_kernel() {
    int i = blockIdx.x * blockDim.x + threadIdx.x;
    if (i < NN * RR) g_cnt[i] = 0;
}

__global__ void count_edges_kernel(const int* __restrict__ edge_index,
                                   const int* __restrict__ edge_type) {
    int e = blockIdx.x * blockDim.x + threadIdx.x;
    if (e >= EE) return;
    int dst = edge_index[EE + e];
    int t = edge_type[e];
    atomicAdd(&g_cnt[dst * RR + t], 1);
}

__global__ void make_inv_kernel() {
    int i = blockIdx.x * blockDim.x + threadIdx.x;
    if (i < NN * RR) {
        int c = g_cnt[i];
        g_inv[i] = (c > 0) ? (1.f / (float)c) : 0.f;
    }
}

__global__ void build_W_kernel(const float* __restrict__ comp,
                               const float* __restrict__ bases,
                               const float* __restrict__ root, int l) {
    int k = blockIdx.x, o = threadIdx.x;
    float acc;
    if (k < RR * HH) {
        int r = k >> 7, i = k & 127;
        acc = 0.f;
#pragma unroll
        for (int b = 0; b < BB; b++)
            acc += comp[(l * RR + r) * BB + b] *
                   bases[((l * BB + b) * HH + i) * HH + o];
    } else {
        int i = k - RR * HH;
        acc = root[(l * HH + i) * HH + o];
    }
    g_Wh[k * HH + o] = __float2half(acc);
}

__global__ void zero_s_kernel() {
    size_t i = (size_t)blockIdx.x * blockDim.x + threadIdx.x;
    size_t tot = (size_t)NN * RR * HH / 4;
    float4* p = (float4*)g_s;
    if (i < tot) p[i] = make_float4(0.f, 0.f, 0.f, 0.f);
}

__global__ void scatter_kernel(const int* __restrict__ edge_index,
                               const int* __restrict__ edge_type,
                               const float* __restrict__ x) {
    int e = blockIdx.x * 8 + (threadIdx.x >> 5);
    if (e >= EE) return;
    int lane = threadIdx.x & 31;
    int src = edge_index[e];
    int dst = edge_index[EE + e];
    int t = edge_type[e];
    float4 v = ((const float4*)(x + src * HH))[lane];
    float* p = g_s + (size_t)(dst * RR + t) * HH + lane * 4;
    atomicAdd(p + 0, v.x);
    atomicAdd(p + 1, v.y);
    atomicAdd(p + 2, v.z);
    atomicAdd(p + 3, v.w);
}

// GEMM: g_h[n,o] = sum_k A[n,k]*Wcat[k,o] + bias[o]
//   A[n,k] = g_s[n,k]*g_inv[n, k/128]  (k < 1024),  x[n, k-1024] (k >= 1024)
// fp16 mma.sync m16n8k16, fp32 accumulate. Block = 128 rows x 128 cols, K-tiles of 32.
__global__ void __launch_bounds__(256) gemm_kernel(const float* __restrict__ x,
                                                   const float* __restrict__ bias) {
    __shared__ __align__(16) __half As[2][128][40];
    __shared__ __align__(16) __half Bs[2][128][40];

    int tid = threadIdx.x;
    int warp = tid >> 5, lane = tid & 31;
    int warp_m = warp >> 2, warp_n = warp & 3;   // 2 x 4 warps
    int m0 = blockIdx.x * 128;
    int gr = lane >> 2, tc = lane & 3;

    float acc[4][4][4];
#pragma unroll
    for (int a = 0; a < 4; a++)
#pragma unroll
        for (int b = 0; b < 4; b++)
#pragma unroll
            for (int c = 0; c < 4; c++) acc[a][b][c] = 0.f;

    const int NKT = KTOT / 32;  // 36

    // ---- tile loaders ----
    auto load_tiles = [&](int st, int k0) {
        {   // A: 128 rows x 32 cols, fp32 -> scale -> fp16
            int c = tid & 31;
            int r8 = tid >> 5;
            int k = k0 + c;
#pragma unroll
            for (int j = 0; j < 16; j++) {
                int row = j * 8 + r8;
                int n = m0 + row;
                float v = 0.f;
                if (n < NN) {
                    if (k < RR * HH)
                        v = g_s[n * (RR * HH) + k] * g_inv[n * RR + (k >> 7)];
                    else
                        v = x[n * HH + (k - RR * HH)];
                }
                As[st][row][c] = __float2half(v);
            }
        }
        {   // B: Wcat rows k0..k0+31, store transposed Bs[o][k]
            int o = tid & 127;
            int kb = tid >> 7;  // 0..1
#pragma unroll
            for (int j = 0; j < 16; j++) {
                int k = kb + j * 2;
                Bs[st][o][k] = g_Wh[(k0 + k) * HH + o];
            }
        }
    };

    load_tiles(0, 0);
    __syncthreads();

    for (int t = 0; t < NKT; t++) {
        int st = t & 1;
        if (t + 1 < NKT) load_tiles((t + 1) & 1, (t + 1) * 32);

#pragma unroll
        for (int kk = 0; kk < 32; kk += 16) {
            unsigned bf[4][2];
#pragma unroll
            for (int nt = 0; nt < 4; nt++) {
                int n0 = warp_n * 32 + nt * 8 + gr;
                bf[nt][0] = *(const unsigned*)&Bs[st][n0][kk + 2 * tc];
                bf[nt][1] = *(const unsigned*)&Bs[st][n0][kk + 2 * tc + 8];
            }
#pragma unroll
            for (int mt = 0; mt < 4; mt++) {
                int r0 = warp_m * 64 + mt * 16 + gr;
                unsigned a0 = *(const unsigned*)&As[st][r0][kk + 2 * tc];
                unsigned a1 = *(const unsigned*)&As[st][r0 + 8][kk + 2 * tc];
                unsigned a2 = *(const unsigned*)&As[st][r0][kk + 2 * tc + 8];
                unsigned a3 = *(const unsigned*)&As[st][r0 + 8][kk + 2 * tc + 8];
#pragma unroll
                for (int nt = 0; nt < 4; nt++) {
                    asm volatile(
                        "mma.sync.aligned.m16n8k16.row.col.f32.f16.f16.f32 "
                        "{%0,%1,%2,%3}, {%4,%5,%6,%7}, {%8,%9}, {%0,%1,%2,%3};\n"
                        : "+f"(acc[mt][nt][0]), "+f"(acc[mt][nt][1]),
                          "+f"(acc[mt][nt][2]), "+f"(acc[mt][nt][3])
                        : "r"(a0), "r"(a1), "r"(a2), "r"(a3),
                          "r"(bf[nt][0]), "r"(bf[nt][1]));
                }
            }
        }
        __syncthreads();
    }

    // epilogue: + bias, store fp32
#pragma unroll
    for (int mt = 0; mt < 4; mt++) {
#pragma unroll
        for (int nt = 0; nt < 4; nt++) {
            int row = m0 + warp_m * 64 + mt * 16 + gr;
            int col = warp_n * 32 + nt * 8 + 2 * tc;
            float b0 = bias[col], b1 = bias[col + 1];
            if (row < NN) {
                g_h[row * HH + col] = acc[mt][nt][0] + b0;
                g_h[row * HH + col + 1] = acc[mt][nt][1] + b1;
            }
            if (row + 8 < NN) {
                g_h[(row + 8) * HH + col] = acc[mt][nt][2] + b0;
                g_h[(row + 8) * HH + col + 1] = acc[mt][nt][3] + b1;
            }
        }
    }
}

__global__ void zero_stats_kernel() {
    int o = threadIdx.x;
    g_sum[o] = 0.0;
    g_sumsq[o] = 0.0;
}

__global__ void stats_kernel() {
    __shared__ double ssum[256], ssq[256];
    int tid = threadIdx.x;
    int col = tid & 127;
    int half_ = tid >> 7;
    double s = 0.0, q = 0.0;
    for (int n = blockIdx.x * 2 + half_; n < NN; n += gridDim.x * 2) {
        float v = g_h[n * HH + col];
        s += v;
        q += (double)v * v;
    }
    ssum[tid] = s;
    ssq[tid] = q;
    __syncthreads();
    if (tid < 128) {
        atomicAdd(&g_sum[col], ssum[tid] + ssum[tid + 128]);
        atomicAdd(&g_sumsq[col], ssq[tid] + ssq[tid + 128]);
    }
}

__global__ void update_kernel(float* __restrict__ x,
                              const float* __restrict__ gamma,
                              const float* __restrict__ beta) {
    int n = blockIdx.x, o = threadIdx.x;
    double mu = g_sum[o] / (double)NN;
    double var = g_sumsq[o] / (double)NN - mu * mu;
    float rstd = rsqrtf((float)var + BN_EPS);
    float h = g_h[n * HH + o];
    float bn = gamma[o] * (h - (float)mu) * rstd + beta[o];
    x[n * HH + o] += fmaxf(bn, 0.f);
}

// ---------------- launch -----------------------------------------------------

extern "C" void kernel_launch(void* const* d_in, const int* in_sizes, int n_in,
                              void* d_out, int out_size) {
    const int* x_ids = (const int*)d_in[0];
    const int* edge_index = (const int*)d_in[1];
    const int* edge_type = (const int*)d_in[2];
    const float* node_feat = (const float*)d_in[3];
    const float* emb = (const float*)d_in[4];
    const float* feat_w = (const float*)d_in[5];
    const float* feat_b = (const float*)d_in[6];
    const float* virt = (const float*)d_in[7];
    const float* bases = (const float*)d_in[8];
    const float* comp = (const float*)d_in[9];
    const float* root = (const float*)d_in[10];
    const float* bias = (const float*)d_in[11];
    const float* gamma = (const float*)d_in[12];
    const float* beta = (const float*)d_in[13];
    float* x = (float*)d_out;   // use the output buffer as the live node state

    init_x_kernel<<<NN, HH>>>(x, x_ids, node_feat, emb, feat_w, feat_b, virt);
    zero_cnt_kernel<<<(NN * RR + 255) / 256, 256>>>();
    count_edges_kernel<<<(EE + 255) / 256, 256>>>(edge_index, edge_type);
    make_inv_kernel<<<(NN * RR + 255) / 256, 256>>>();

    for (int l = 0; l < LL; l++) {
        build_W_kernel<<<KTOT, HH>>>(comp, bases, root, l);
        zero_s_kernel<<<(NN * RR * HH / 4 + 255) / 256, 256>>>();
        scatter_kernel<<<(EE + 7) / 8, 256>>>(edge_index, edge_type, x);
        gemm_kernel<<<(NN + 127) / 128, 256>>>(x, bias + l * HH);
        zero_stats_kernel<<<1, HH>>>();
        stats_kernel<<<256, 256>>>();
        update_kernel<<<NN, HH>>>(x, gamma + l * HH, beta + l * HH);
    }
}

// round 2
// speedup vs baseline: 3.4878x; 3.4878x over previous
#include <cuda_runtime.h>
#include <cuda_fp16.h>

#define NN 50000
#define EE 800000
#define RR 8
#define BB 8
#define HH 128
#define LL 3
#define FDIM 6
#define KTOT 1152          // R*H + H (root folded in)
#define NSEG (NN * RR)     // 400000
#define NBLK 391           // ceil(NSEG/1024)
#define BN_EPS 1e-5f

// ---------------- scratch (static device memory) ----------------------------
__device__ __half g_sh[(size_t)NSEG * HH];   // per-(node,rel) mean(x[src]) fp16 (102.4 MB)
__device__ __half g_xh[NN * HH];             // x in fp16 (per layer)
__device__ float  g_h[NN * HH];              // pre-BN layer output
__device__ int    g_cnt[NSEG];
__device__ int    g_off[NSEG + 1];
__device__ int    g_cursor[NSEG];
__device__ int    g_bsum[512];
__device__ int    g_src[EE];                 // edge src sorted by (dst,rel)
__device__ __half g_WhT[HH * KTOT];          // W transposed: [o][k]
__device__ double g_sum[HH], g_sumsq[HH];

// ---------------- init / CSR build ------------------------------------------

__global__ void init_x_kernel(float* __restrict__ x,
                              const int* __restrict__ x_ids,
                              const float* __restrict__ node_feat,
                              const float* __restrict__ emb,
                              const float* __restrict__ feat_w,
                              const float* __restrict__ feat_b,
                              const float* __restrict__ virt) {
    int n = blockIdx.x, o = threadIdx.x;
    float f = feat_b[o];
#pragma unroll
    for (int d = 0; d < FDIM; d++)
        f += node_feat[n * FDIM + d] * feat_w[o * FDIM + d];
    x[n * HH + o] = emb[x_ids[n] * HH + o] + fmaxf(f, 0.f) + virt[o];
}

__global__ void zero_cnt_kernel() {
    int i = blockIdx.x * blockDim.x + threadIdx.x;
    if (i < NSEG) g_cnt[i] = 0;
}

__global__ void count_edges_kernel(const int* __restrict__ edge_index,
                                   const int* __restrict__ edge_type) {
    int e = blockIdx.x * blockDim.x + threadIdx.x;
    if (e >= EE) return;
    atomicAdd(&g_cnt[edge_index[EE + e] * RR + edge_type[e]], 1);
}

__global__ void scan_block_kernel() {
    __shared__ int sm[1024];
    int i = blockIdx.x * 1024 + threadIdx.x;
    int v = (i < NSEG) ? g_cnt[i] : 0;
    sm[threadIdx.x] = v;
    __syncthreads();
    for (int s = 1; s < 1024; s <<= 1) {
        int t = (threadIdx.x >= s) ? sm[threadIdx.x - s] : 0;
        __syncthreads();
        sm[threadIdx.x] += t;
        __syncthreads();
    }
    if (i < NSEG) g_off[i] = sm[threadIdx.x] - v;   // exclusive within block
    if (threadIdx.x == 1023) g_bsum[blockIdx.x] = sm[1023];
}

__global__ void scan_sums_kernel() {
    __shared__ int sm[512];
    int v = (threadIdx.x < NBLK) ? g_bsum[threadIdx.x] : 0;
    sm[threadIdx.x] = v;
    __syncthreads();
    for (int s = 1; s < 512; s <<= 1) {
        int t = (threadIdx.x >= s) ? sm[threadIdx.x - s] : 0;
        __syncthreads();
        sm[threadIdx.x] += t;
        __syncthreads();
    }
    g_bsum[threadIdx.x] = sm[threadIdx.x] - v;      // exclusive
}

__global__ void scan_add_kernel() {
    int i = blockIdx.x * 1024 + threadIdx.x;
    if (i < NSEG) {
        int o = g_off[i] + g_bsum[blockIdx.x];
        g_off[i] = o;
        g_cursor[i] = o;
    }
    if (i == 0) g_off[NSEG] = EE;
}

__global__ void csr_fill_kernel(const int* __restrict__ edge_index,
                                const int* __restrict__ edge_type) {
    int e = blockIdx.x * blockDim.x + threadIdx.x;
    if (e >= EE) return;
    int seg = edge_index[EE + e] * RR + edge_type[e];
    int pos = atomicAdd(&g_cursor[seg], 1);
    g_src[pos] = edge_index[e];
}

// ---------------- per-layer kernels -----------------------------------------

// W transposed: g_WhT[o][k]; block = col o (128 blocks), threads stride over k.
__global__ void build_W_kernel(const float* __restrict__ comp,
                               const float* __restrict__ bases,
                               const float* __restrict__ root, int l) {
    int o = blockIdx.x;
    for (int k = threadIdx.x; k < KTOT; k += blockDim.x) {
        float acc;
        if (k < RR * HH) {
            int r = k >> 7, i = k & 127;
            acc = 0.f;
#pragma unroll
            for (int b = 0; b < BB; b++)
                acc += comp[(l * RR + r) * BB + b] *
                       bases[((l * BB + b) * HH + i) * HH + o];
        } else {
            acc = root[(l * HH + (k - RR * HH)) * HH + o];
        }
        g_WhT[o * KTOT + k] = __float2half(acc);
    }
}

__global__ void xhalf_kernel(const float* __restrict__ x) {
    int i = blockIdx.x * blockDim.x + threadIdx.x;
    if (i < NN * HH / 2) {
        float2 v = ((const float2*)x)[i];
        ((__half2*)g_xh)[i] = __floats2half2_rn(v.x, v.y);
    }
}

// warp-per-segment gather-sum: no atomics, writes mean directly in fp16.
__global__ void seg_sum_kernel(const float* __restrict__ x) {
    int seg = blockIdx.x * 8 + (threadIdx.x >> 5);
    if (seg >= NSEG) return;
    int lane = threadIdx.x & 31;
    int beg = g_off[seg], end = g_off[seg + 1];
    float a0 = 0.f, a1 = 0.f, a2 = 0.f, a3 = 0.f;
    for (int e = beg; e < end; e++) {
        int src = g_src[e];
        float4 v = ((const float4*)(x + src * HH))[lane];
        a0 += v.x; a1 += v.y; a2 += v.z; a3 += v.w;
    }
    float inv = (end > beg) ? 1.f / (float)(end - beg) : 0.f;
    __half2 h0 = __floats2half2_rn(a0 * inv, a1 * inv);
    __half2 h1 = __floats2half2_rn(a2 * inv, a3 * inv);
    uint2 o;
    o.x = *(unsigned*)&h0;
    o.y = *(unsigned*)&h1;
    ((uint2*)(g_sh + (size_t)seg * HH))[lane] = o;
}

// GEMM: g_h[n,o] = sum_k A[n,k]*W[k,o] + bias[o]
//   A[n,k] = g_sh[n*1024+k] (k<1024, inv already applied), g_xh[n,k-1024] else.
__global__ void __launch_bounds__(256) gemm_kernel(const float* __restrict__ bias) {
    __shared__ __align__(16) __half As[2][128][40];
    __shared__ __align__(16) __half Bs[2][128][40];

    int tid = threadIdx.x;
    int warp = tid >> 5, lane = tid & 31;
    int warp_m = warp >> 2, warp_n = warp & 3;   // 2 x 4 warps
    int m0 = blockIdx.x * 128;
    int gr = lane >> 2, tc = lane & 3;

    float acc[4][4][4];
#pragma unroll
    for (int a = 0; a < 4; a++)
#pragma unroll
        for (int b = 0; b < 4; b++)
#pragma unroll
            for (int c = 0; c < 4; c++) acc[a][b][c] = 0.f;

    const int NKT = KTOT / 32;  // 36

    auto load_tiles = [&](int st, int k0) {
        // A: 128x32 halves, 8-half (16B) vector loads
        const __half* base;
        int stride;
        if (k0 < RR * HH) { base = g_sh + k0; stride = RR * HH; }
        else              { base = g_xh + (k0 - RR * HH); stride = HH; }
        int row = tid >> 2;
        int c8 = (tid & 3) * 8;
#pragma unroll
        for (int j = 0; j < 2; j++) {
            int r = row + j * 64;
            int n = m0 + r;
            uint4 v = make_uint4(0u, 0u, 0u, 0u);
            if (n < NN) v = *(const uint4*)(base + (size_t)n * stride + c8);
            *(uint4*)&As[st][r][c8] = v;
        }
        // B: Bs[o][k] from pre-transposed g_WhT
        int o = tid & 127;
        int s8 = (tid >> 7) * 8;
#pragma unroll
        for (int j = 0; j < 2; j++) {
            int kk = s8 + j * 16;
            *(uint4*)&Bs[st][o][kk] = *(const uint4*)(g_WhT + o * KTOT + k0 + kk);
        }
    };

    load_tiles(0, 0);
    __syncthreads();

    for (int t = 0; t < NKT; t++) {
        int st = t & 1;
        if (t + 1 < NKT) load_tiles((t + 1) & 1, (t + 1) * 32);

#pragma unroll
        for (int kk = 0; kk < 32; kk += 16) {
            unsigned bf[4][2];
#pragma unroll
            for (int nt = 0; nt < 4; nt++) {
                int n0 = warp_n * 32 + nt * 8 + gr;
                bf[nt][0] = *(const unsigned*)&Bs[st][n0][kk + 2 * tc];
                bf[nt][1] = *(const unsigned*)&Bs[st][n0][kk + 2 * tc + 8];
            }
#pragma unroll
            for (int mt = 0; mt < 4; mt++) {
                int r0 = warp_m * 64 + mt * 16 + gr;
                unsigned a0 = *(const unsigned*)&As[st][r0][kk + 2 * tc];
                unsigned a1 = *(const unsigned*)&As[st][r0 + 8][kk + 2 * tc];
                unsigned a2 = *(const unsigned*)&As[st][r0][kk + 2 * tc + 8];
                unsigned a3 = *(const unsigned*)&As[st][r0 + 8][kk + 2 * tc + 8];
#pragma unroll
                for (int nt = 0; nt < 4; nt++) {
                    asm volatile(
                        "mma.sync.aligned.m16n8k16.row.col.f32.f16.f16.f32 "
                        "{%0,%1,%2,%3}, {%4,%5,%6,%7}, {%8,%9}, {%0,%1,%2,%3};\n"
                        : "+f"(acc[mt][nt][0]), "+f"(acc[mt][nt][1]),
                          "+f"(acc[mt][nt][2]), "+f"(acc[mt][nt][3])
                        : "r"(a0), "r"(a1), "r"(a2), "r"(a3),
                          "r"(bf[nt][0]), "r"(bf[nt][1]));
                }
            }
        }
        __syncthreads();
    }

#pragma unroll
    for (int mt = 0; mt < 4; mt++) {
#pragma unroll
        for (int nt = 0; nt < 4; nt++) {
            int row = m0 + warp_m * 64 + mt * 16 + gr;
            int col = warp_n * 32 + nt * 8 + 2 * tc;
            float b0 = bias[col], b1 = bias[col + 1];
            if (row < NN) {
                g_h[row * HH + col] = acc[mt][nt][0] + b0;
                g_h[row * HH + col + 1] = acc[mt][nt][1] + b1;
            }
            if (row + 8 < NN) {
                g_h[(row + 8) * HH + col] = acc[mt][nt][2] + b0;
                g_h[(row + 8) * HH + col + 1] = acc[mt][nt][3] + b1;
            }
        }
    }
}

__global__ void zero_stats_kernel() {
    int o = threadIdx.x;
    g_sum[o] = 0.0;
    g_sumsq[o] = 0.0;
}

__global__ void stats_kernel() {
    __shared__ double ssum[256], ssq[256];
    int tid = threadIdx.x;
    int col = tid & 127;
    int half_ = tid >> 7;
    double s = 0.0, q = 0.0;
    for (int n = blockIdx.x * 2 + half_; n < NN; n += gridDim.x * 2) {
        float v = g_h[n * HH + col];
        s += v;
        q += (double)v * v;
    }
    ssum[tid] = s;
    ssq[tid] = q;
    __syncthreads();
    if (tid < 128) {
        atomicAdd(&g_sum[col], ssum[tid] + ssum[tid + 128]);
        atomicAdd(&g_sumsq[col], ssq[tid] + ssq[tid + 128]);
    }
}

__global__ void update_kernel(float* __restrict__ x,
                              const float* __restrict__ gamma,
                              const float* __restrict__ beta) {
    int n = blockIdx.x, o = threadIdx.x;
    double mu = g_sum[o] / (double)NN;
    double var = g_sumsq[o] / (double)NN - mu * mu;
    float rstd = rsqrtf((float)var + BN_EPS);
    float h = g_h[n * HH + o];
    float bn = gamma[o] * (h - (float)mu) * rstd + beta[o];
    x[n * HH + o] += fmaxf(bn, 0.f);
}

// ---------------- launch -----------------------------------------------------

extern "C" void kernel_launch(void* const* d_in, const int* in_sizes, int n_in,
                              void* d_out, int out_size) {
    const int* x_ids = (const int*)d_in[0];
    const int* edge_index = (const int*)d_in[1];
    const int* edge_type = (const int*)d_in[2];
    const float* node_feat = (const float*)d_in[3];
    const float* emb = (const float*)d_in[4];
    const float* feat_w = (const float*)d_in[5];
    const float* feat_b = (const float*)d_in[6];
    const float* virt = (const float*)d_in[7];
    const float* bases = (const float*)d_in[8];
    const float* comp = (const float*)d_in[9];
    const float* root = (const float*)d_in[10];
    const float* bias = (const float*)d_in[11];
    const float* gamma = (const float*)d_in[12];
    const float* beta = (const float*)d_in[13];
    float* x = (float*)d_out;

    init_x_kernel<<<NN, HH>>>(x, x_ids, node_feat, emb, feat_w, feat_b, virt);

    // CSR build (once)
    zero_cnt_kernel<<<(NSEG + 255) / 256, 256>>>();
    count_edges_kernel<<<(EE + 255) / 256, 256>>>(edge_index, edge_type);
    scan_block_kernel<<<NBLK, 1024>>>();
    scan_sums_kernel<<<1, 512>>>();
    scan_add_kernel<<<NBLK, 1024>>>();
    csr_fill_kernel<<<(EE + 255) / 256, 256>>>(edge_index, edge_type);

    for (int l = 0; l < LL; l++) {
        build_W_kernel<<<HH, 256>>>(comp, bases, root, l);
        xhalf_kernel<<<(NN * HH / 2 + 255) / 256, 256>>>(x);
        seg_sum_kernel<<<(NSEG + 7) / 8, 256>>>(x);
        gemm_kernel<<<(NN + 127) / 128, 256>>>(bias + l * HH);
        zero_stats_kernel<<<1, HH>>>();
        stats_kernel<<<256, 256>>>();
        update_kernel<<<NN, HH>>>(x, gamma + l * HH, beta + l * HH);
    }
}

// round 3
// speedup vs baseline: 4.6319x; 1.3280x over previous
#include <cuda_runtime.h>
#include <cuda_fp16.h>
#include <stdint.h>

#define NN 50000
#define EE 800000
#define RR 8
#define BB 8
#define HH 128
#define LL 3
#define FDIM 6
#define KTOT 1152          // R*H + H (root folded in)
#define NSEG (NN * RR)     // 400000
#define NBLK 391           // ceil(NSEG/1024)
#define BN_EPS 1e-5f
#define NST 3              // GEMM pipeline stages
#define NKT (KTOT / 32)    // 36 K-tiles

// ---------------- scratch (static device memory) ----------------------------
__device__ __half g_sh[(size_t)NSEG * HH];   // per-(node,rel) mean fp16 (102.4 MB)
__device__ __half g_xh[NN * HH];             // x in fp16
__device__ float  g_h[NN * HH];              // pre-BN layer output
__device__ int    g_cnt[NSEG];
__device__ int    g_off[NSEG + 1];
__device__ int    g_cursor[NSEG];
__device__ int    g_bsum[512];
__device__ int    g_src[EE];                 // edge src sorted by (dst,rel)
__device__ __half g_WhT[HH * KTOT];          // W transposed: [o][k]
__device__ double g_sum[HH], g_sumsq[HH];

// ---------------- cp.async helpers -------------------------------------------
#define CP_ASYNC16(dst_u32, src, sz) \
    asm volatile("cp.async.cg.shared.global [%0], [%1], 16, %2;\n" \
                 :: "r"(dst_u32), "l"(src), "r"(sz))
#define CP_COMMIT() asm volatile("cp.async.commit_group;\n")
#define CP_WAIT2()  asm volatile("cp.async.wait_group 2;\n")

// ---------------- init / CSR build ------------------------------------------

__global__ void init_x_kernel(float* __restrict__ x,
                              const int* __restrict__ x_ids,
                              const float* __restrict__ node_feat,
                              const float* __restrict__ emb,
                              const float* __restrict__ feat_w,
                              const float* __restrict__ feat_b,
                              const float* __restrict__ virt) {
    int n = blockIdx.x, o = threadIdx.x;
    float f = feat_b[o];
#pragma unroll
    for (int d = 0; d < FDIM; d++)
        f += node_feat[n * FDIM + d] * feat_w[o * FDIM + d];
    float v = emb[x_ids[n] * HH + o] + fmaxf(f, 0.f) + virt[o];
    x[n * HH + o] = v;
    g_xh[n * HH + o] = __float2half(v);
}

__global__ void zero_cnt_kernel() {
    int i = blockIdx.x * blockDim.x + threadIdx.x;
    if (i < NSEG) g_cnt[i] = 0;
}

__global__ void count_edges_kernel(const int* __restrict__ edge_index,
                                   const int* __restrict__ edge_type) {
    int e = blockIdx.x * blockDim.x + threadIdx.x;
    if (e >= EE) return;
    atomicAdd(&g_cnt[edge_index[EE + e] * RR + edge_type[e]], 1);
}

__global__ void scan_block_kernel() {
    __shared__ int sm[1024];
    int i = blockIdx.x * 1024 + threadIdx.x;
    int v = (i < NSEG) ? g_cnt[i] : 0;
    sm[threadIdx.x] = v;
    __syncthreads();
    for (int s = 1; s < 1024; s <<= 1) {
        int t = (threadIdx.x >= s) ? sm[threadIdx.x - s] : 0;
        __syncthreads();
        sm[threadIdx.x] += t;
        __syncthreads();
    }
    if (i < NSEG) g_off[i] = sm[threadIdx.x] - v;
    if (threadIdx.x == 1023) g_bsum[blockIdx.x] = sm[1023];
}

__global__ void scan_sums_kernel() {
    __shared__ int sm[512];
    int v = (threadIdx.x < NBLK) ? g_bsum[threadIdx.x] : 0;
    sm[threadIdx.x] = v;
    __syncthreads();
    for (int s = 1; s < 512; s <<= 1) {
        int t = (threadIdx.x >= s) ? sm[threadIdx.x - s] : 0;
        __syncthreads();
        sm[threadIdx.x] += t;
        __syncthreads();
    }
    g_bsum[threadIdx.x] = sm[threadIdx.x] - v;
}

__global__ void scan_add_kernel() {
    int i = blockIdx.x * 1024 + threadIdx.x;
    if (i < NSEG) {
        int o = g_off[i] + g_bsum[blockIdx.x];
        g_off[i] = o;
        g_cursor[i] = o;
    }
    if (i == 0) g_off[NSEG] = EE;
}

__global__ void csr_fill_kernel(const int* __restrict__ edge_index,
                                const int* __restrict__ edge_type) {
    int e = blockIdx.x * blockDim.x + threadIdx.x;
    if (e >= EE) return;
    int seg = edge_index[EE + e] * RR + edge_type[e];
    int pos = atomicAdd(&g_cursor[seg], 1);
    g_src[pos] = edge_index[e];
}

// ---------------- per-layer kernels -----------------------------------------

// W transposed + zero BN stats for this layer.
__global__ void build_W_kernel(const float* __restrict__ comp,
                               const float* __restrict__ bases,
                               const float* __restrict__ root, int l) {
    int o = blockIdx.x;
    if (threadIdx.x == 0) { g_sum[o] = 0.0; g_sumsq[o] = 0.0; }
    for (int k = threadIdx.x; k < KTOT; k += blockDim.x) {
        float acc;
        if (k < RR * HH) {
            int r = k >> 7, i = k & 127;
            acc = 0.f;
#pragma unroll
            for (int b = 0; b < BB; b++)
                acc += comp[(l * RR + r) * BB + b] *
                       bases[((l * BB + b) * HH + i) * HH + o];
        } else {
            acc = root[(l * HH + (k - RR * HH)) * HH + o];
        }
        g_WhT[o * KTOT + k] = __float2half(acc);
    }
}

// warp-per-segment gather-sum from fp16 x; no atomics, writes mean in fp16.
__global__ void seg_sum_kernel() {
    int seg = blockIdx.x * 8 + (threadIdx.x >> 5);
    if (seg >= NSEG) return;
    int lane = threadIdx.x & 31;
    int beg = g_off[seg], end = g_off[seg + 1];
    float a0 = 0.f, a1 = 0.f, a2 = 0.f, a3 = 0.f;
    for (int e = beg; e < end; e++) {
        int src = g_src[e];
        uint2 v = ((const uint2*)(g_xh + src * HH))[lane];
        __half2 h0 = *(__half2*)&v.x;
        __half2 h1 = *(__half2*)&v.y;
        float2 f0 = __half22float2(h0);
        float2 f1 = __half22float2(h1);
        a0 += f0.x; a1 += f0.y; a2 += f1.x; a3 += f1.y;
    }
    float inv = (end > beg) ? 1.f / (float)(end - beg) : 0.f;
    __half2 o0 = __floats2half2_rn(a0 * inv, a1 * inv);
    __half2 o1 = __floats2half2_rn(a2 * inv, a3 * inv);
    uint2 o;
    o.x = *(unsigned*)&o0;
    o.y = *(unsigned*)&o1;
    ((uint2*)(g_sh + (size_t)seg * HH))[lane] = o;
}

// GEMM: g_h[n,o] = sum_k A[n,k]*W[k,o] + bias[o]; BN stats fused into epilogue.
// A[n,k] = g_sh[n*1024+k] (k<1024), g_xh[n,k-1024] else.
// 3-stage cp.async pipeline, fp16 mma m16n8k16 fp32-acc.
__global__ void __launch_bounds__(256) gemm_kernel(const float* __restrict__ bias) {
    extern __shared__ __align__(16) char dynsm[];
    __half(*As)[128][40] = (__half(*)[128][40])dynsm;
    __half(*Bs)[128][40] = (__half(*)[128][40])(dynsm + NST * 128 * 40 * 2);
    float* red = (float*)(dynsm + 2 * NST * 128 * 40 * 2);  // [2][128][2]

    int tid = threadIdx.x;
    int warp = tid >> 5, lane = tid & 31;
    int warp_m = warp >> 2, warp_n = warp & 3;   // 2 x 4 warps
    int m0 = blockIdx.x * 128;
    int gr = lane >> 2, tc = lane & 3;

    float acc[4][4][4];
#pragma unroll
    for (int a = 0; a < 4; a++)
#pragma unroll
        for (int b = 0; b < 4; b++)
#pragma unroll
            for (int c = 0; c < 4; c++) acc[a][b][c] = 0.f;

    // per-thread load coords
    int arow = tid >> 2;           // 0..63
    int ac8 = (tid & 3) * 8;       // A column (halves)
    int bo = tid & 127;            // B output col
    int bs8 = (tid >> 7) * 8;      // B k offset

    auto load_tiles = [&](int st, int k0) {
        const __half* base;
        int stride;
        if (k0 < RR * HH) { base = g_sh + k0; stride = RR * HH; }
        else              { base = g_xh + (k0 - RR * HH); stride = HH; }
#pragma unroll
        for (int j = 0; j < 2; j++) {
            int r = arow + j * 64;
            int n = m0 + r;
            int sz = 16;
            if (n >= NN) { n = NN - 1; sz = 0; }   // zero-fill OOB rows
            uint32_t dst = (uint32_t)__cvta_generic_to_shared(&As[st][r][ac8]);
            CP_ASYNC16(dst, base + (size_t)n * stride + ac8, sz);
        }
#pragma unroll
        for (int j = 0; j < 2; j++) {
            int kk = bs8 + j * 16;
            uint32_t dst = (uint32_t)__cvta_generic_to_shared(&Bs[st][bo][kk]);
            CP_ASYNC16(dst, g_WhT + bo * KTOT + k0 + kk, 16);
        }
    };

    load_tiles(0, 0); CP_COMMIT();
    load_tiles(1, 32); CP_COMMIT();

    for (int t = 0; t < NKT; t++) {
        int st = t % NST;
        if (t + 2 < NKT) load_tiles((t + 2) % NST, (t + 2) * 32);
        CP_COMMIT();
        CP_WAIT2();
        __syncthreads();

#pragma unroll
        for (int kk = 0; kk < 32; kk += 16) {
            unsigned bf[4][2];
#pragma unroll
            for (int nt = 0; nt < 4; nt++) {
                int n0 = warp_n * 32 + nt * 8 + gr;
                bf[nt][0] = *(const unsigned*)&Bs[st][n0][kk + 2 * tc];
                bf[nt][1] = *(const unsigned*)&Bs[st][n0][kk + 2 * tc + 8];
            }
#pragma unroll
            for (int mt = 0; mt < 4; mt++) {
                int r0 = warp_m * 64 + mt * 16 + gr;
                unsigned a0 = *(const unsigned*)&As[st][r0][kk + 2 * tc];
                unsigned a1 = *(const unsigned*)&As[st][r0 + 8][kk + 2 * tc];
                unsigned a2 = *(const unsigned*)&As[st][r0][kk + 2 * tc + 8];
                unsigned a3 = *(const unsigned*)&As[st][r0 + 8][kk + 2 * tc + 8];
#pragma unroll
                for (int nt = 0; nt < 4; nt++) {
                    asm volatile(
                        "mma.sync.aligned.m16n8k16.row.col.f32.f16.f16.f32 "
                        "{%0,%1,%2,%3}, {%4,%5,%6,%7}, {%8,%9}, {%0,%1,%2,%3};\n"
                        : "+f"(acc[mt][nt][0]), "+f"(acc[mt][nt][1]),
                          "+f"(acc[mt][nt][2]), "+f"(acc[mt][nt][3])
                        : "r"(a0), "r"(a1), "r"(a2), "r"(a3),
                          "r"(bf[nt][0]), "r"(bf[nt][1]));
                }
            }
        }
        __syncthreads();
    }

    // epilogue: + bias, store fp32, accumulate BN stats
    float s[4][2] = {}, q[4][2] = {};
#pragma unroll
    for (int mt = 0; mt < 4; mt++) {
#pragma unroll
        for (int nt = 0; nt < 4; nt++) {
            int row = m0 + warp_m * 64 + mt * 16 + gr;
            int col = warp_n * 32 + nt * 8 + 2 * tc;
            float b0 = bias[col], b1 = bias[col + 1];
            if (row < NN) {
                float h0 = acc[mt][nt][0] + b0;
                float h1 = acc[mt][nt][1] + b1;
                g_h[row * HH + col] = h0;
                g_h[row * HH + col + 1] = h1;
                s[nt][0] += h0; q[nt][0] += h0 * h0;
                s[nt][1] += h1; q[nt][1] += h1 * h1;
            }
            if (row + 8 < NN) {
                float h2 = acc[mt][nt][2] + b0;
                float h3 = acc[mt][nt][3] + b1;
                g_h[(row + 8) * HH + col] = h2;
                g_h[(row + 8) * HH + col + 1] = h3;
                s[nt][0] += h2; q[nt][0] += h2 * h2;
                s[nt][1] += h3; q[nt][1] += h3 * h3;
            }
        }
    }
    // reduce over gr (lane = gr*4 + tc): offsets 16, 8, 4 keep tc fixed
#pragma unroll
    for (int nt = 0; nt < 4; nt++) {
#pragma unroll
        for (int idx = 0; idx < 2; idx++) {
            float v = s[nt][idx], w = q[nt][idx];
#pragma unroll
            for (int off = 16; off >= 4; off >>= 1) {
                v += __shfl_down_sync(0xffffffffu, v, off);
                w += __shfl_down_sync(0xffffffffu, w, off);
            }
            if (gr == 0) {
                int col = warp_n * 32 + nt * 8 + 2 * tc + idx;
                red[(warp_m * 128 + col) * 2 + 0] = v;
                red[(warp_m * 128 + col) * 2 + 1] = w;
            }
        }
    }
    __syncthreads();
    if (tid < 128) {
        int col = tid;
        atomicAdd(&g_sum[col],   (double)(red[col * 2] + red[(128 + col) * 2]));
        atomicAdd(&g_sumsq[col], (double)(red[col * 2 + 1] + red[(128 + col) * 2 + 1]));
    }
}

__global__ void update_kernel(float* __restrict__ x,
                              const float* __restrict__ gamma,
                              const float* __restrict__ beta) {
    int n = blockIdx.x, o = threadIdx.x;
    double mu = g_sum[o] / (double)NN;
    double var = g_sumsq[o] / (double)NN - mu * mu;
    float rstd = rsqrtf((float)var + BN_EPS);
    float h = g_h[n * HH + o];
    float bn = gamma[o] * (h - (float)mu) * rstd + beta[o];
    float nx = x[n * HH + o] + fmaxf(bn, 0.f);
    x[n * HH + o] = nx;
    g_xh[n * HH + o] = __float2half(nx);
}

// ---------------- launch -----------------------------------------------------

extern "C" void kernel_launch(void* const* d_in, const int* in_sizes, int n_in,
                              void* d_out, int out_size) {
    const int* x_ids = (const int*)d_in[0];
    const int* edge_index = (const int*)d_in[1];
    const int* edge_type = (const int*)d_in[2];
    const float* node_feat = (const float*)d_in[3];
    const float* emb = (const float*)d_in[4];
    const float* feat_w = (const float*)d_in[5];
    const float* feat_b = (const float*)d_in[6];
    const float* virt = (const float*)d_in[7];
    const float* bases = (const float*)d_in[8];
    const float* comp = (const float*)d_in[9];
    const float* root = (const float*)d_in[10];
    const float* bias = (const float*)d_in[11];
    const float* gamma = (const float*)d_in[12];
    const float* beta = (const float*)d_in[13];
    float* x = (float*)d_out;

    const int GEMM_SMEM = 2 * NST * 128 * 40 * 2 + 2 * 128 * 2 * 4;  // 63488
    static int attr_set = 0;
    if (!attr_set) {
        cudaFuncSetAttribute(gemm_kernel,
                             cudaFuncAttributeMaxDynamicSharedMemorySize, GEMM_SMEM);
        attr_set = 1;
    }

    init_x_kernel<<<NN, HH>>>(x, x_ids, node_feat, emb, feat_w, feat_b, virt);

    // CSR build (once per call)
    zero_cnt_kernel<<<(NSEG + 255) / 256, 256>>>();
    count_edges_kernel<<<(EE + 255) / 256, 256>>>(edge_index, edge_type);
    scan_block_kernel<<<NBLK, 1024>>>();
    scan_sums_kernel<<<1, 512>>>();
    scan_add_kernel<<<NBLK, 1024>>>();
    csr_fill_kernel<<<(EE + 255) / 256, 256>>>(edge_index, edge_type);

    for (int l = 0; l < LL; l++) {
        build_W_kernel<<<HH, 256>>>(comp, bases, root, l);
        seg_sum_kernel<<<(NSEG + 7) / 8, 256>>>();
        gemm_kernel<<<(NN + 127) / 128, 256, GEMM_SMEM>>>(bias + l * HH);
        update_kernel<<<NN, HH>>>(x, gamma + l * HH, beta + l * HH);
    }
}

// round 5
// speedup vs baseline: 5.5406x; 1.1962x over previous
#include <cuda_runtime.h>
#include <cuda_fp16.h>
#include <stdint.h>

#define NN 50000
#define EE 800000
#define RR 8
#define BB 8
#define HH 128
#define LL 3
#define FDIM 6
#define KTOT 1152          // R*H + H (root folded in)
#define NSEG (NN * RR)     // 400000
#define NBLK 391           // ceil(NSEG/1024)
#define BN_EPS 1e-5f
#define NST 3              // GEMM pipeline stages
#define KC 64              // K-chunk in halves (128B rows)
#define NKT (KTOT / KC)    // 18 chunks
#define STAGE_BYTES 32768  // A 16KB + B 16KB

// ---------------- scratch (static device memory) ----------------------------
// Tiled + pre-swizzled A: [chunk][n][64 halves]; element (n,k) at plane k/64,
// row n, byte ((k&63)*2) ^ ((n&7)<<4).  Chunks 0..15 = seg means, 16..17 = x.
__device__ __half g_A[(size_t)NKT * NN * KC + 8192];   // 115.2 MB + pad
__device__ __half g_WhT[NKT * HH * KC];                // tiled+swizzled W
__device__ float  g_h[NN * HH];                        // pre-BN layer output
__device__ int    g_cnt[NSEG];
__device__ int    g_off[NSEG + 1];
__device__ int    g_cursor[NSEG];
__device__ int    g_bsum[512];
__device__ int    g_src[EE];
__device__ double g_sum[HH], g_sumsq[HH];

// ---------------- PTX helpers -------------------------------------------------
#define MBARRIER_INIT(addr, cnt) \
    asm volatile("mbarrier.init.shared.b64 [%0], %1;" :: "r"(addr), "r"(cnt) : "memory")
#define MBARRIER_EXPECT_TX(addr, bytes) \
    asm volatile("mbarrier.arrive.expect_tx.shared.b64 _, [%0], %1;" \
                 :: "r"(addr), "r"(bytes) : "memory")
#define MBARRIER_WAIT_PARITY(addr, par) do {                                   \
    asm volatile(                                                              \
        "{\n\t.reg .pred P1;\n\t"                                              \
        "WAIT_LOOP_%=:\n\t"                                                    \
        "mbarrier.try_wait.parity.acquire.cta.shared::cta.b64 P1, [%0], %1, 0x989680;\n\t" \
        "@P1 bra.uni WAIT_DONE_%=;\n\t"                                        \
        "bra.uni WAIT_LOOP_%=;\n\t"                                            \
        "WAIT_DONE_%=:\n\t}"                                                   \
        :: "r"(addr), "r"(par) : "memory");                                    \
} while (0)
#define BULK_G2S(dst_u32, src, bytes, mbar) \
    asm volatile("cp.async.bulk.shared::cluster.global.mbarrier::complete_tx::bytes " \
                 "[%0], [%1], %2, [%3];" \
                 :: "r"(dst_u32), "l"(src), "r"(bytes), "r"(mbar) : "memory")

// swizzled byte-offset within a 128B row
__device__ __forceinline__ uint32_t swz(int row, int hcol) {
    return (uint32_t)((hcol * 2) ^ ((row & 7) << 4));
}

// ---------------- init / CSR build ------------------------------------------

__global__ void init_x_kernel(float* __restrict__ x,
                              const int* __restrict__ x_ids,
                              const float* __restrict__ node_feat,
                              const float* __restrict__ emb,
                              const float* __restrict__ feat_w,
                              const float* __restrict__ feat_b,
                              const float* __restrict__ virt) {
    int n = blockIdx.x, o = threadIdx.x;
    int gt = blockIdx.x * blockDim.x + threadIdx.x;
    if (gt < NSEG) g_cnt[gt] = 0;
    float f = feat_b[o];
#pragma unroll
    for (int d = 0; d < FDIM; d++)
        f += node_feat[n * FDIM + d] * feat_w[o * FDIM + d];
    float v = emb[x_ids[n] * HH + o] + fmaxf(f, 0.f) + virt[o];
    x[n * HH + o] = v;
    int c = 16 + (o >> 6);
    char* p = (char*)g_A + ((size_t)c * NN + n) * 128 + swz(n, o & 63);
    *(__half*)p = __float2half(v);
}

__global__ void count_edges_kernel(const int* __restrict__ edge_index,
                                   const int* __restrict__ edge_type) {
    int e = blockIdx.x * blockDim.x + threadIdx.x;
    if (e >= EE) return;
    atomicAdd(&g_cnt[edge_index[EE + e] * RR + edge_type[e]], 1);
}

__global__ void scan_block_kernel() {
    __shared__ int sm[1024];
    int i = blockIdx.x * 1024 + threadIdx.x;
    int v = (i < NSEG) ? g_cnt[i] : 0;
    sm[threadIdx.x] = v;
    __syncthreads();
    for (int s = 1; s < 1024; s <<= 1) {
        int t = (threadIdx.x >= s) ? sm[threadIdx.x - s] : 0;
        __syncthreads();
        sm[threadIdx.x] += t;
        __syncthreads();
    }
    if (i < NSEG) g_off[i] = sm[threadIdx.x] - v;
    if (threadIdx.x == 1023) g_bsum[blockIdx.x] = sm[1023];
}

__global__ void scan_sums_kernel() {
    __shared__ int sm[512];
    int v = (threadIdx.x < NBLK) ? g_bsum[threadIdx.x] : 0;
    sm[threadIdx.x] = v;
    __syncthreads();
    for (int s = 1; s < 512; s <<= 1) {
        int t = (threadIdx.x >= s) ? sm[threadIdx.x - s] : 0;
        __syncthreads();
        sm[threadIdx.x] += t;
        __syncthreads();
    }
    g_bsum[threadIdx.x] = sm[threadIdx.x] - v;
}

__global__ void scan_add_kernel() {
    int i = blockIdx.x * 1024 + threadIdx.x;
    if (i < NSEG) {
        int o = g_off[i] + g_bsum[blockIdx.x];
        g_off[i] = o;
        g_cursor[i] = o;
    }
    if (i == 0) g_off[NSEG] = EE;
}

__global__ void csr_fill_kernel(const int* __restrict__ edge_index,
                                const int* __restrict__ edge_type) {
    int e = blockIdx.x * blockDim.x + threadIdx.x;
    if (e >= EE) return;
    int seg = edge_index[EE + e] * RR + edge_type[e];
    int pos = atomicAdd(&g_cursor[seg], 1);
    g_src[pos] = edge_index[e];
}

// ---------------- per-layer kernels -----------------------------------------

// W tiled+swizzled + zero BN stats.
__global__ void build_W_kernel(const float* __restrict__ comp,
                               const float* __restrict__ bases,
                               const float* __restrict__ root, int l) {
    int o = blockIdx.x;
    if (threadIdx.x == 0) { g_sum[o] = 0.0; g_sumsq[o] = 0.0; }
    for (int k = threadIdx.x; k < KTOT; k += blockDim.x) {
        float acc;
        if (k < RR * HH) {
            int r = k >> 7, i = k & 127;
            acc = 0.f;
#pragma unroll
            for (int b = 0; b < BB; b++)
                acc += comp[(l * RR + r) * BB + b] *
                       bases[((l * BB + b) * HH + i) * HH + o];
        } else {
            acc = root[(l * HH + (k - RR * HH)) * HH + o];
        }
        int c = k >> 6;
        char* p = (char*)g_WhT + ((size_t)c * HH + o) * 128 + swz(o, k & 63);
        *(__half*)p = __float2half(acc);
    }
}

// warp-per-segment gather-sum; reads x planes (16,17), writes mean planes (2r, 2r+1).
__global__ void seg_sum_kernel() {
    int seg = blockIdx.x * 8 + (threadIdx.x >> 5);
    if (seg >= NSEG) return;
    int lane = threadIdx.x & 31;
    int cx = 16 + (lane >> 4);               // source x plane for this lane
    uint32_t bcol = (uint32_t)((lane & 15) * 8);
    int beg = g_off[seg], end = g_off[seg + 1];
    float a0 = 0.f, a1 = 0.f, a2 = 0.f, a3 = 0.f;
    const char* xbase = (const char*)g_A + (size_t)cx * NN * 128;
    for (int e = beg; e < end; e++) {
        int src = g_src[e];
        uint2 v = *(const uint2*)(xbase + (size_t)src * 128 + (bcol ^ ((src & 7) << 4)));
        float2 f0 = __half22float2(*(__half2*)&v.x);
        float2 f1 = __half22float2(*(__half2*)&v.y);
        a0 += f0.x; a1 += f0.y; a2 += f1.x; a3 += f1.y;
    }
    float inv = (end > beg) ? 1.f / (float)(end - beg) : 0.f;
    __half2 o0 = __floats2half2_rn(a0 * inv, a1 * inv);
    __half2 o1 = __floats2half2_rn(a2 * inv, a3 * inv);
    uint2 o;
    o.x = *(unsigned*)&o0;
    o.y = *(unsigned*)&o1;
    int n = seg >> 3, r = seg & 7;
    int cd = 2 * r + (lane >> 4);
    char* dst = (char*)g_A + ((size_t)cd * NN + n) * 128 + (bcol ^ ((n & 7) << 4));
    *(uint2*)dst = o;
}

// GEMM: g_h = A[50000 x 1152] * W[1152 x 128] + bias, BN stats fused.
// Bulk-async loads (2 per stage), 3 stages, mma.sync m16n8k16 fp32-acc.
__global__ void __launch_bounds__(256) gemm_kernel(const float* __restrict__ bias) {
    extern __shared__ __align__(1024) char dynsm[];
    uint32_t smem_base;
    asm("{ .reg .u64 t; cvta.to.shared.u64 t, %1; cvt.u32.u64 %0, t; }"
        : "=r"(smem_base) : "l"(dynsm));
    const uint32_t MBAR = smem_base;           // 3 x 8B
    float* red = (float*)(dynsm + 64);          // [2][128][2] = 2KB
    char* stages = dynsm + 4096;
    const uint32_t STAGES_U32 = smem_base + 4096;

    int tid = threadIdx.x;
    int warp = tid >> 5, lane = tid & 31;
    int warp_m = warp >> 2, warp_n = warp & 3;   // 2 x 4 warps
    int m0 = blockIdx.x * 128;
    int gr = lane >> 2, tc = lane & 3;

    if (tid == 0) {
#pragma unroll
        for (int s = 0; s < NST; s++) MBARRIER_INIT(MBAR + s * 8, 1);
    }
    __syncthreads();

    // prologue: issue chunks 0..NST-1
    if (tid == 0) {
#pragma unroll
        for (int s = 0; s < NST; s++) {
            MBARRIER_EXPECT_TX(MBAR + s * 8, STAGE_BYTES);
            const char* srcA = (const char*)g_A + ((size_t)s * NN + m0) * 128;
            const char* srcB = (const char*)g_WhT + (size_t)s * HH * 128;
            BULK_G2S(STAGES_U32 + s * STAGE_BYTES, srcA, 16384, MBAR + s * 8);
            BULK_G2S(STAGES_U32 + s * STAGE_BYTES + 16384, srcB, 16384, MBAR + s * 8);
        }
    }

    float acc[4][4][4];
#pragma unroll
    for (int a = 0; a < 4; a++)
#pragma unroll
        for (int b = 0; b < 4; b++)
#pragma unroll
            for (int c = 0; c < 4; c++) acc[a][b][c] = 0.f;

    for (int t = 0; t < NKT; t++) {
        int s = t % NST;
        MBARRIER_WAIT_PARITY(MBAR + s * 8, (t / NST) & 1);

        const char* sA = stages + s * STAGE_BYTES;
        const char* sB = sA + 16384;
#pragma unroll
        for (int kk = 0; kk < KC; kk += 16) {
            int hc0 = kk + 2 * tc;
            unsigned bf[4][2];
#pragma unroll
            for (int nt = 0; nt < 4; nt++) {
                int n0 = warp_n * 32 + nt * 8 + gr;
                const char* bp = sB + n0 * 128;
                bf[nt][0] = *(const unsigned*)(bp + swz(n0, hc0));
                bf[nt][1] = *(const unsigned*)(bp + swz(n0, hc0 + 8));
            }
#pragma unroll
            for (int mt = 0; mt < 4; mt++) {
                int r0 = warp_m * 64 + mt * 16 + gr;
                const char* ap0 = sA + r0 * 128;
                const char* ap1 = sA + (r0 + 8) * 128;
                unsigned a0 = *(const unsigned*)(ap0 + swz(r0, hc0));
                unsigned a1 = *(const unsigned*)(ap1 + swz(r0 + 8, hc0));
                unsigned a2 = *(const unsigned*)(ap0 + swz(r0, hc0 + 8));
                unsigned a3 = *(const unsigned*)(ap1 + swz(r0 + 8, hc0 + 8));
#pragma unroll
                for (int nt = 0; nt < 4; nt++) {
                    asm volatile(
                        "mma.sync.aligned.m16n8k16.row.col.f32.f16.f16.f32 "
                        "{%0,%1,%2,%3}, {%4,%5,%6,%7}, {%8,%9}, {%0,%1,%2,%3};\n"
                        : "+f"(acc[mt][nt][0]), "+f"(acc[mt][nt][1]),
                          "+f"(acc[mt][nt][2]), "+f"(acc[mt][nt][3])
                        : "r"(a0), "r"(a1), "r"(a2), "r"(a3),
                          "r"(bf[nt][0]), "r"(bf[nt][1]));
                }
            }
        }
        __syncthreads();
        if (tid == 0 && t + NST < NKT) {
            int u = t + NST;
            MBARRIER_EXPECT_TX(MBAR + s * 8, STAGE_BYTES);
            const char* srcA = (const char*)g_A + ((size_t)u * NN + m0) * 128;
            const char* srcB = (const char*)g_WhT + (size_t)u * HH * 128;
            BULK_G2S(STAGES_U32 + s * STAGE_BYTES, srcA, 16384, MBAR + s * 8);
            BULK_G2S(STAGES_U32 + s * STAGE_BYTES + 16384, srcB, 16384, MBAR + s * 8);
        }
    }

    // epilogue: + bias, store fp32, BN stats
    float s4[4][2] = {}, q4[4][2] = {};
#pragma unroll
    for (int mt = 0; mt < 4; mt++) {
#pragma unroll
        for (int nt = 0; nt < 4; nt++) {
            int row = m0 + warp_m * 64 + mt * 16 + gr;
            int col = warp_n * 32 + nt * 8 + 2 * tc;
            float b0 = bias[col], b1 = bias[col + 1];
            if (row < NN) {
                float h0 = acc[mt][nt][0] + b0;
                float h1 = acc[mt][nt][1] + b1;
                g_h[row * HH + col] = h0;
                g_h[row * HH + col + 1] = h1;
                s4[nt][0] += h0; q4[nt][0] += h0 * h0;
                s4[nt][1] += h1; q4[nt][1] += h1 * h1;
            }
            if (row + 8 < NN) {
                float h2 = acc[mt][nt][2] + b0;
                float h3 = acc[mt][nt][3] + b1;
                g_h[(row + 8) * HH + col] = h2;
                g_h[(row + 8) * HH + col + 1] = h3;
                s4[nt][0] += h2; q4[nt][0] += h2 * h2;
                s4[nt][1] += h3; q4[nt][1] += h3 * h3;
            }
        }
    }
#pragma unroll
    for (int nt = 0; nt < 4; nt++) {
#pragma unroll
        for (int idx = 0; idx < 2; idx++) {
            float v = s4[nt][idx], w = q4[nt][idx];
#pragma unroll
            for (int off = 16; off >= 4; off >>= 1) {
                v += __shfl_down_sync(0xffffffffu, v, off);
                w += __shfl_down_sync(0xffffffffu, w, off);
            }
            if (gr == 0) {
                int col = warp_n * 32 + nt * 8 + 2 * tc + idx;
                red[(warp_m * 128 + col) * 2 + 0] = v;
                red[(warp_m * 128 + col) * 2 + 1] = w;
            }
        }
    }
    __syncthreads();
    if (tid < 128) {
        int col = tid;
        atomicAdd(&g_sum[col],   (double)(red[col * 2] + red[(128 + col) * 2]));
        atomicAdd(&g_sumsq[col], (double)(red[col * 2 + 1] + red[(128 + col) * 2 + 1]));
    }
}

__global__ void update_kernel(float* __restrict__ x,
                              const float* __restrict__ gamma,
                              const float* __restrict__ beta) {
    int i = blockIdx.x * blockDim.x + threadIdx.x;
    if (i >= NN * HH) return;
    int n = i >> 7, o = i & 127;
    double mu = g_sum[o] / (double)NN;
    double var = g_sumsq[o] / (double)NN - mu * mu;
    float rstd = rsqrtf((float)var + BN_EPS);
    float h = g_h[i];
    float bn = gamma[o] * (h - (float)mu) * rstd + beta[o];
    float nx = x[i] + fmaxf(bn, 0.f);
    x[i] = nx;
    int c = 16 + (o >> 6);
    char* p = (char*)g_A + ((size_t)c * NN + n) * 128 + swz(n, o & 63);
    *(__half*)p = __float2half(nx);
}

// ---------------- launch -----------------------------------------------------

extern "C" void kernel_launch(void* const* d_in, const int* in_sizes, int n_in,
                              void* d_out, int out_size) {
    const int* x_ids = (const int*)d_in[0];
    const int* edge_index = (const int*)d_in[1];
    const int* edge_type = (const int*)d_in[2];
    const float* node_feat = (const float*)d_in[3];
    const float* emb = (const float*)d_in[4];
    const float* feat_w = (const float*)d_in[5];
    const float* feat_b = (const float*)d_in[6];
    const float* virt = (const float*)d_in[7];
    const float* bases = (const float*)d_in[8];
    const float* comp = (const float*)d_in[9];
    const float* root = (const float*)d_in[10];
    const float* bias = (const float*)d_in[11];
    const float* gamma = (const float*)d_in[12];
    const float* beta = (const float*)d_in[13];
    float* x = (float*)d_out;

    const int GEMM_SMEM = 4096 + NST * STAGE_BYTES;   // 102400
    static int attr_set = 0;
    if (!attr_set) {
        cudaFuncSetAttribute(gemm_kernel,
                             cudaFuncAttributeMaxDynamicSharedMemorySize, GEMM_SMEM);
        attr_set = 1;
    }

    init_x_kernel<<<NN, HH>>>(x, x_ids, node_feat, emb, feat_w, feat_b, virt);
    count_edges_kernel<<<(EE + 255) / 256, 256>>>(edge_index, edge_type);
    scan_block_kernel<<<NBLK, 1024>>>();
    scan_sums_kernel<<<1, 512>>>();
    scan_add_kernel<<<NBLK, 1024>>>();
    csr_fill_kernel<<<(EE + 255) / 256, 256>>>(edge_index, edge_type);

    for (int l = 0; l < LL; l++) {
        build_W_kernel<<<HH, 256>>>(comp, bases, root, l);
        seg_sum_kernel<<<(NSEG + 7) / 8, 256>>>();
        gemm_kernel<<<(NN + 127) / 128, 256, GEMM_SMEM>>>(bias + l * HH);
        update_kernel<<<(NN * HH + 255) / 256, 256>>>(x, gamma + l * HH, beta + l * HH);
    }
}